// round 15
// baseline (speedup 1.0000x reference)
#include <cuda_runtime.h>
#include <cuda_bf16.h>

#define B       2
#define NV      16384
#define MOBS    12000
#define NF      16384
#define BINF    256
#define FBW     64.0f            // face bins per unit |f|   (range [0,4))
#define VBW     32.0f            // vertex bins per unit |c| (range [0,8))
#define NSAMP   2048             // phase-1 sample: every 8th face
#define TNN     64               // nn block size
#define FLT_BIG 3.4e38f

// ---- device scratch (no allocations allowed) ----
__device__ float4 g_fc[B * NF];        // original-order (cx,cy,cz,|c|^2 fma)
__device__ float4 g_fn[B * NF];        // next centroid
__device__ float4 g_nm[B * NF];        // next normal
__device__ float4 g_fsorted[B * NF];   // |f|-bin-sorted faces
__device__ int    g_forig[B * NF];     // original index of sorted face
__device__ float4 g_vsorted[B * NV];   // |c|-bin-sorted verts (xyz, bitcast orig)
__device__ int    g_histF[B * BINF];
__device__ int    g_histV[B * BINF];
__device__ int    g_startF[B * (BINF + 1)];
__device__ int    g_startV[B * (BINF + 1)];
__device__ int    g_curF[B * BINF];
__device__ int    g_curV[B * BINF];
__device__ int    g_gidx[B * NV];      // final argmin face (original index)
__device__ float  g_partial[64];

// norm^2 with fma contraction, ascending (the critical rounding form)
__device__ __forceinline__ float norm2_fma(float x, float y, float z) {
    return __fmaf_rn(z, z, __fmaf_rn(y, y, __fmul_rn(x, x)));
}
// the R13-passing score: s = rn( fma(-2, dot, cn) + fw ),
// dot = fma(cz,fz, fma(cy,fy, rn(cx*fx)))
__device__ __forceinline__ float score(float cx, float cy, float cz, float cn,
                                       float4 f) {
    float dot = __fmaf_rn(cz, f.z, __fmaf_rn(cy, f.y, __fmul_rn(cx, f.x)));
    return __fadd_rn(__fmaf_rn(-2.0f, dot, cn), f.w);
}

// ---------------------------------------------------------------------------
__global__ void zero_kernel() {
    int t = blockIdx.x * blockDim.x + threadIdx.x;
    if (t < B * BINF) { g_histF[t] = 0; g_histV[t] = 0; }
}

// ---------------------------------------------------------------------------
// prep: faces (fc/fn/nm + |f| histogram) and vertices (|c| histogram).
// B*NF == B*NV so one thread does face t and vertex t.
// ---------------------------------------------------------------------------
__global__ void prep_kernel(const float* __restrict__ obs_c,
                            const float* __restrict__ obs_n,
                            const int* __restrict__ faces32,
                            const float* __restrict__ cloth_c) {
    __shared__ int s_is64;
    if (threadIdx.x == 0) {
        int orv = 0;
        #pragma unroll
        for (int j = 0; j < 64; ++j) orv |= faces32[2 * j + 1];
        s_is64 = (orv == 0) ? 1 : 0;
    }
    __syncthreads();

    int t = blockIdx.x * blockDim.x + threadIdx.x;
    if (t >= B * NF) return;
    int b = t / NF;

    int i0, i1, i2;
    if (s_is64) {
        i0 = faces32[t * 6 + 0]; i1 = faces32[t * 6 + 2]; i2 = faces32[t * 6 + 4];
    } else {
        i0 = faces32[t * 3 + 0]; i1 = faces32[t * 3 + 1]; i2 = faces32[t * 3 + 2];
    }
    i0 = min(max(i0, 0), MOBS - 1);
    i1 = min(max(i1, 0), MOBS - 1);
    i2 = min(max(i2, 0), MOBS - 1);

    const float* oc = obs_c + (long long)b * MOBS * 3;
    const float* on = obs_n + (long long)b * MOBS * 3;

    float cx = __fdiv_rn(__fadd_rn(__fadd_rn(oc[i0*3+0], oc[i1*3+0]), oc[i2*3+0]), 3.0f);
    float cy = __fdiv_rn(__fadd_rn(__fadd_rn(oc[i0*3+1], oc[i1*3+1]), oc[i2*3+1]), 3.0f);
    float cz = __fdiv_rn(__fadd_rn(__fadd_rn(oc[i0*3+2], oc[i1*3+2]), oc[i2*3+2]), 3.0f);
    float fn2 = norm2_fma(cx, cy, cz);
    g_fc[t] = make_float4(cx, cy, cz, fn2);

    int fb = min(BINF - 1, (int)(sqrtf(fn2) * FBW));
    atomicAdd(&g_histF[b * BINF + fb], 1);

    // vertex t: |c| histogram
    {
        const float* vp = cloth_c + (long long)t * 3;
        float vn = norm2_fma(vp[0], vp[1], vp[2]);
        int vb = min(BINF - 1, (int)(sqrtf(vn) * VBW));
        atomicAdd(&g_histV[b * BINF + vb], 1);
    }

    float ax = on[i0*3+0], ay = on[i0*3+1], az = on[i0*3+2];
    float bx = on[i1*3+0], by = on[i1*3+1], bz = on[i1*3+2];
    float dx = on[i2*3+0], dy = on[i2*3+1], dz = on[i2*3+2];

    g_fn[t] = make_float4(
        __fdiv_rn(__fadd_rn(__fadd_rn(ax, bx), dx), 3.0f),
        __fdiv_rn(__fadd_rn(__fadd_rn(ay, by), dy), 3.0f),
        __fdiv_rn(__fadd_rn(__fadd_rn(az, bz), dz), 3.0f), 0.0f);

    float e1x = __fsub_rn(bx, ax), e1y = __fsub_rn(by, ay), e1z = __fsub_rn(bz, az);
    float e2x = __fsub_rn(dx, ax), e2y = __fsub_rn(dy, ay), e2z = __fsub_rn(dz, az);
    float nx = __fmaf_rn(e1y, e2z, -__fmul_rn(e1z, e2y));
    float ny = __fmaf_rn(e1z, e2x, -__fmul_rn(e1x, e2z));
    float nz = __fmaf_rn(e1x, e2y, -__fmul_rn(e1y, e2x));
    float nrm = __fadd_rn(__fsqrt_rn(norm2_fma(nx, ny, nz)), 1e-12f);
    g_nm[t] = make_float4(__fdiv_rn(nx, nrm), __fdiv_rn(ny, nrm),
                          __fdiv_rn(nz, nrm), 0.0f);
}

// ---------------------------------------------------------------------------
// scan: 4 independent 256-bin exclusive scans (threads 0..3, sequential each)
// Also initializes scatter cursors to the bin starts.
// ---------------------------------------------------------------------------
__global__ void scan_kernel() {
    int k = threadIdx.x;            // 0..3 : {F b0, F b1, V b0, V b1}
    if (k >= 2 * B) return;
    int isV = k / B, b = k % B;
    const int* h = (isV ? g_histV : g_histF) + b * BINF;
    int* st = (isV ? g_startV : g_startF) + b * (BINF + 1);
    int* cu = (isV ? g_curV : g_curF) + b * BINF;
    int acc = 0;
    for (int i = 0; i < BINF; ++i) {
        st[i] = acc; cu[i] = acc; acc += h[i];
    }
    st[BINF] = acc;
}

// ---------------------------------------------------------------------------
// scatter: faces into |f|-bin order, vertices into |c|-bin order.
// Order within a bin is atomics-arbitrary; final argmin is made order-
// independent by the (score, orig_idx) total-order comparator in nn_kernel.
// ---------------------------------------------------------------------------
__global__ void scatter_kernel(const float* __restrict__ cloth_c) {
    int t = blockIdx.x * blockDim.x + threadIdx.x;
    if (t >= B * NF) return;
    int b = t / NF;

    float4 f = g_fc[t];
    int fb = min(BINF - 1, (int)(sqrtf(f.w) * FBW));
    int fp = atomicAdd(&g_curF[b * BINF + fb], 1);
    g_fsorted[b * NF + fp] = f;
    g_forig[b * NF + fp] = t - b * NF;

    const float* vp = cloth_c + (long long)t * 3;
    float vx = vp[0], vy = vp[1], vz = vp[2];
    float vn = norm2_fma(vx, vy, vz);
    int vb = min(BINF - 1, (int)(sqrtf(vn) * VBW));
    int vpos = atomicAdd(&g_curV[b * BINF + vb], 1);
    g_vsorted[b * NV + vpos] = make_float4(vx, vy, vz,
                                           __int_as_float(t - b * NF));
}

// ---------------------------------------------------------------------------
// nn: phase 1 — upper bound s0 from every-8th face (smem broadcast tile);
//     phase 2 — exact rescore of faces with |f| in [|c|-R, |c|+R] (warp-
//     union bin range), comparator (s, orig_idx) lexicographic.
// Pruning is conservative: R = sqrt(max(s0,0)+1e-4)+2e-3 covers the <=5e-6
// absolute score rounding and fp32 norm errors, so the window provably
// contains the reference's argmin face.
// ---------------------------------------------------------------------------
__global__ __launch_bounds__(TNN) void nn_kernel() {
    __shared__ float4 samp[NSAMP];

    int b = blockIdx.y;

    for (int i = threadIdx.x; i < NSAMP; i += TNN)
        samp[i] = g_fc[b * NF + i * 8];
    __syncthreads();

    float4 v = g_vsorted[b * NV + blockIdx.x * TNN + threadIdx.x];
    float cx = v.x, cy = v.y, cz = v.z;
    int   orig = __float_as_int(v.w);
    float cn = norm2_fma(cx, cy, cz);

    float s0 = FLT_BIG;
    #pragma unroll 8
    for (int j = 0; j < NSAMP; ++j)
        s0 = fminf(s0, score(cx, cy, cz, cn, samp[j]));

    float cnorm = sqrtf(cn);
    float R  = sqrtf(fmaxf(s0, 0.0f) + 1e-4f) + 2e-3f;
    float lo = cnorm - R, hi = cnorm + R;
    #pragma unroll
    for (int o = 16; o > 0; o >>= 1) {
        lo = fminf(lo, __shfl_xor_sync(0xffffffffu, lo, o));
        hi = fmaxf(hi, __shfl_xor_sync(0xffffffffu, hi, o));
    }
    int blo = max(0, (int)(fmaxf(lo, 0.0f) * FBW));
    int bhi = min(BINF - 1, (int)(fmaxf(hi, 0.0f) * FBW));
    int rs = g_startF[b * (BINF + 1) + blo];
    int re = g_startF[b * (BINF + 1) + bhi + 1];

    float best = FLT_BIG;
    int   bidx = 0x7fffffff;
    const float4* fs = g_fsorted + b * NF;
    const int*    fo = g_forig + b * NF;
    #pragma unroll 4
    for (int r = rs; r < re; ++r) {
        float4 f = __ldg(&fs[r]);      // uniform address across warp
        int   oi = __ldg(&fo[r]);
        float s  = score(cx, cy, cz, cn, f);
        bool better = (s < best) || (s == best && oi < bidx);
        best = better ? s : best;
        bidx = better ? oi : bidx;
    }
    g_gidx[b * NV + orig] = bidx;
}

// ---------------------------------------------------------------------------
// epi: plane distance, interpenetration, weight; emits block partial sums
// ---------------------------------------------------------------------------
__global__ void epi_kernel(const float* __restrict__ cloth_n,
                           const int* __restrict__ iterp,
                           float* __restrict__ out) {
    int n = blockIdx.x * blockDim.x + threadIdx.x;

    int iter = iterp ? iterp[0] : 60000;  // low word valid for LE int64 too
    int it = iter - 50000; if (it < 0) it = 0;
    double prog = (double)it / 100000.0;
    if (prog > 1.0) prog = 1.0;
    float weight = (float)(1e-3 + (5e3 - 1e-3) * prog);

    float val = 0.0f;
    if (n < NV) {
        float acc = 0.0f;
        #pragma unroll
        for (int b = 0; b < B; ++b) {
            int bi = g_gidx[b * NV + n];
            float4 p  = g_fn[b * NF + bi];
            float4 nm = g_nm[b * NF + bi];
            const float* q = cloth_n + ((long long)b * NV + n) * 3;
            float dx = __fsub_rn(q[0], p.x);
            float dy = __fsub_rn(q[1], p.y);
            float dz = __fsub_rn(q[2], p.z);
            float dist = __fmaf_rn(dz, nm.z, __fmaf_rn(dy, nm.y, __fmul_rn(dx, nm.x)));
            float t2 = __fsub_rn(1e-3f, dist);
            t2 = t2 > 0.0f ? t2 : 0.0f;
            acc = __fadd_rn(acc, __fmul_rn(__fmul_rn(t2, t2), t2));
        }
        val = __fmul_rn(__fmul_rn(acc, 0.5f), weight);
        out[1 + n] = val;
    }

    __shared__ float sh[256];
    sh[threadIdx.x] = val;
    __syncthreads();
    for (int k = 128; k > 0; k >>= 1) {
        if (threadIdx.x < k) sh[threadIdx.x] += sh[threadIdx.x + k];
        __syncthreads();
    }
    if (threadIdx.x == 0) g_partial[blockIdx.x] = sh[0];
}

// ---------------------------------------------------------------------------
// red: out[0] = sum of 64 block partials (single warp, deterministic tree)
// ---------------------------------------------------------------------------
__global__ void red_kernel(float* __restrict__ out) {
    int l = threadIdx.x;            // 32 threads
    float s = g_partial[l] + g_partial[l + 32];
    #pragma unroll
    for (int o = 16; o > 0; o >>= 1) s += __shfl_xor_sync(0xffffffffu, s, o);
    if (l == 0) out[0] = s;
}

// ---------------------------------------------------------------------------
// Resolve inputs BY SIZE (tolerant to elements-vs-bytes conventions)
// ---------------------------------------------------------------------------
extern "C" void kernel_launch(void* const* d_in, const int* in_sizes, int n_in,
                              void* d_out, int out_size) {
    const float* cloth_curr = nullptr;
    const float* cloth_next = nullptr;
    const float* obs_curr   = nullptr;
    const float* obs_next   = nullptr;
    const int*   faces32    = nullptr;
    const int*   iterp      = nullptr;

    int n_big = 0, n_obs = 0;
    for (int i = 0; i < n_in; ++i) {
        int s = in_sizes[i];
        if (s == 98304 || s == 393216) {
            if (n_big == 0)      cloth_curr = (const float*)d_in[i];
            else if (n_big == 1) cloth_next = (const float*)d_in[i];
            else                 faces32    = (const int*)d_in[i];
            ++n_big;
        } else if (s == 786432) {
            faces32 = (const int*)d_in[i];
        } else if (s == 72000 || s == 288000) {
            if (n_obs == 0) obs_curr = (const float*)d_in[i];
            else            obs_next = (const float*)d_in[i];
            ++n_obs;
        } else if (s == 1 || s == 4 || s == 8) {
            iterp = (const int*)d_in[i];
        }
    }

    float* out = (float*)d_out;

    zero_kernel<<<2, 256>>>();
    prep_kernel<<<(B * NF + 255) / 256, 256>>>(obs_curr, obs_next, faces32,
                                               cloth_curr);
    scan_kernel<<<1, 32>>>();
    scatter_kernel<<<(B * NF + 255) / 256, 256>>>(cloth_curr);

    dim3 grid(NV / TNN, B);         // (256, 2) = 512 CTAs
    nn_kernel<<<grid, TNN>>>();

    epi_kernel<<<NV / 256, 256>>>(cloth_next, iterp, out);
    red_kernel<<<1, 32>>>(out);
}

// round 16
// speedup vs baseline: 2.1655x; 2.1655x over previous
#include <cuda_runtime.h>
#include <cuda_bf16.h>

#define B       2
#define NV      16384
#define MOBS    12000
#define NF      16384
#define NCHUNK  8
#define FPC     (NF / NCHUNK)   // 2048 faces per chunk == one smem tile
#define T2      256             // threads for nn kernel (each handles 2 verts)
#define VPC     (T2 * 2)        // vertices per CTA = 512
#define SCR_EPS 1e-4f           // screen margin >> assoc-rounding bound (~1e-6)
#define FLT_BIG 3.4e38f

// ---- device scratch (no allocations allowed) ----
__device__ float4 g_fc[B * NF];            // (cx, cy, cz, |c|^2 fma-chain)
__device__ float4 g_fn[B * NF];            // next centroid (xyz)
__device__ float4 g_nm[B * NF];            // next normal (xyz, normalized)
__device__ float  g_best[NCHUNK][B * NV];  // per-chunk min EXACT score
__device__ int    g_bidx[NCHUNK][B * NV];  // per-chunk argmin face idx
__device__ float  g_partial[64];

// norm^2 with fma contraction, ascending (the critical rounding form)
__device__ __forceinline__ float norm2_fma(float x, float y, float z) {
    return __fmaf_rn(z, z, __fmaf_rn(y, y, __fmul_rn(x, x)));
}

// ---------------------------------------------------------------------------
// Kernel 1: per (batch,face) preprocessing (R13/R14-identical rounding).
// ---------------------------------------------------------------------------
__global__ void prep_kernel(const float* __restrict__ obs_c,
                            const float* __restrict__ obs_n,
                            const int* __restrict__ faces32) {
    __shared__ int s_is64;
    if (threadIdx.x == 0) {
        int orv = 0;
        #pragma unroll
        for (int j = 0; j < 64; ++j) orv |= faces32[2 * j + 1];
        s_is64 = (orv == 0) ? 1 : 0;
    }
    __syncthreads();

    int t = blockIdx.x * blockDim.x + threadIdx.x;
    if (t >= B * NF) return;
    int b = t / NF;

    int i0, i1, i2;
    if (s_is64) {
        i0 = faces32[t * 6 + 0]; i1 = faces32[t * 6 + 2]; i2 = faces32[t * 6 + 4];
    } else {
        i0 = faces32[t * 3 + 0]; i1 = faces32[t * 3 + 1]; i2 = faces32[t * 3 + 2];
    }
    i0 = min(max(i0, 0), MOBS - 1);
    i1 = min(max(i1, 0), MOBS - 1);
    i2 = min(max(i2, 0), MOBS - 1);

    const float* oc = obs_c + (long long)b * MOBS * 3;
    const float* on = obs_n + (long long)b * MOBS * 3;

    float cx = __fdiv_rn(__fadd_rn(__fadd_rn(oc[i0*3+0], oc[i1*3+0]), oc[i2*3+0]), 3.0f);
    float cy = __fdiv_rn(__fadd_rn(__fadd_rn(oc[i0*3+1], oc[i1*3+1]), oc[i2*3+1]), 3.0f);
    float cz = __fdiv_rn(__fadd_rn(__fadd_rn(oc[i0*3+2], oc[i1*3+2]), oc[i2*3+2]), 3.0f);
    g_fc[t] = make_float4(cx, cy, cz, norm2_fma(cx, cy, cz));

    float ax = on[i0*3+0], ay = on[i0*3+1], az = on[i0*3+2];
    float bx = on[i1*3+0], by = on[i1*3+1], bz = on[i1*3+2];
    float dx = on[i2*3+0], dy = on[i2*3+1], dz = on[i2*3+2];

    g_fn[t] = make_float4(
        __fdiv_rn(__fadd_rn(__fadd_rn(ax, bx), dx), 3.0f),
        __fdiv_rn(__fadd_rn(__fadd_rn(ay, by), dy), 3.0f),
        __fdiv_rn(__fadd_rn(__fadd_rn(az, bz), dz), 3.0f), 0.0f);

    float e1x = __fsub_rn(bx, ax), e1y = __fsub_rn(by, ay), e1z = __fsub_rn(bz, az);
    float e2x = __fsub_rn(dx, ax), e2y = __fsub_rn(dy, ay), e2z = __fsub_rn(dz, az);
    float nx = __fmaf_rn(e1y, e2z, -__fmul_rn(e1z, e2y));
    float ny = __fmaf_rn(e1z, e2x, -__fmul_rn(e1x, e2z));
    float nz = __fmaf_rn(e1x, e2y, -__fmul_rn(e1y, e2x));
    float nrm = __fadd_rn(__fsqrt_rn(norm2_fma(nx, ny, nz)), 1e-12f);
    g_nm[t] = make_float4(__fdiv_rn(nx, nrm), __fdiv_rn(ny, nrm),
                          __fdiv_rn(nz, nrm), 0.0f);
}

// ---------------------------------------------------------------------------
// Kernel 2: 1-NN argmin with cheap screen + rare exact rescore.
//   screen:  sa = fma(fx,-2cx, fma(fy,-2cy, fma(fz,-2cz, fw)))   [3 FFMA]
//   exact (R13 bit pattern, only when sa < bestA + SCR_EPS):
//            dot = fma(cz,fz, fma(cy,fy, rn(cx*fx)))
//            s   = rn( fma(-2, dot, cn) + fw )
// Winner = lexicographic min (exact s, face idx) over candidates; the true
// argmin always triggers the screen (|sa - (s - cn)| << SCR_EPS), so the
// result is bit-identical to scoring every face exactly.
// ---------------------------------------------------------------------------
__global__ __launch_bounds__(T2) void nn_kernel(const float* __restrict__ cloth_c) {
    __shared__ float4 sh[FPC];

    int b     = blockIdx.y;
    int chunk = blockIdx.z;
    int n0    = blockIdx.x * VPC + threadIdx.x;
    int n1    = n0 + T2;

    const float* cp0 = cloth_c + ((long long)b * NV + n0) * 3;
    const float* cp1 = cloth_c + ((long long)b * NV + n1) * 3;
    float ax = cp0[0], ay = cp0[1], az = cp0[2];
    float bx = cp1[0], by = cp1[1], bz = cp1[2];
    float an = norm2_fma(ax, ay, az);
    float bn = norm2_fma(bx, by, bz);
    float m2ax = -2.0f * ax, m2ay = -2.0f * ay, m2az = -2.0f * az;
    float m2bx = -2.0f * bx, m2by = -2.0f * by, m2bz = -2.0f * bz;

    int fbase = chunk * FPC;
    const float4* fc = g_fc + b * NF + fbase;
    for (int i = threadIdx.x; i < FPC; i += T2) sh[i] = fc[i];
    __syncthreads();

    float bestSA = FLT_BIG, bestSB = FLT_BIG;   // exact scores
    int   idxA = 0x7fffffff, idxB = 0x7fffffff;
    float thrA = FLT_BIG, thrB = FLT_BIG;       // bestA + SCR_EPS (lazy)
    float bAA = FLT_BIG, bAB = FLT_BIG;         // running approx minima

    #pragma unroll 2
    for (int j = 0; j < FPC; ++j) {
        float4 f = sh[j];
        float saA = __fmaf_rn(f.x, m2ax, __fmaf_rn(f.y, m2ay,
                    __fmaf_rn(f.z, m2az, f.w)));
        float saB = __fmaf_rn(f.x, m2bx, __fmaf_rn(f.y, m2by,
                    __fmaf_rn(f.z, m2bz, f.w)));
        bool tA = saA < thrA;
        bool tB = saB < thrB;
        if (__any_sync(0xffffffffu, tA || tB)) {
            int oi = fbase + j;
            if (tA) {
                float dot = __fmaf_rn(az, f.z, __fmaf_rn(ay, f.y, __fmul_rn(ax, f.x)));
                float s   = __fadd_rn(__fmaf_rn(-2.0f, dot, an), f.w);
                if (s < bestSA || (s == bestSA && oi < idxA)) { bestSA = s; idxA = oi; }
                bAA = fminf(bAA, saA);
                thrA = bAA + SCR_EPS;
            }
            if (tB) {
                float dot = __fmaf_rn(bz, f.z, __fmaf_rn(by, f.y, __fmul_rn(bx, f.x)));
                float s   = __fadd_rn(__fmaf_rn(-2.0f, dot, bn), f.w);
                if (s < bestSB || (s == bestSB && oi < idxB)) { bestSB = s; idxB = oi; }
                bAB = fminf(bAB, saB);
                thrB = bAB + SCR_EPS;
            }
        }
    }
    g_best[chunk][b * NV + n0] = bestSA;
    g_bidx[chunk][b * NV + n0] = idxA;
    g_best[chunk][b * NV + n1] = bestSB;
    g_bidx[chunk][b * NV + n1] = idxB;
}

// ---------------------------------------------------------------------------
// Kernel 3: merge chunks by (exact s, idx) lexicographic (== reference's
// first-index argmin), then plane distance / interpenetration / weight.
// Emits block partial sums.
// ---------------------------------------------------------------------------
__global__ void epi_kernel(const float* __restrict__ cloth_n,
                           const int* __restrict__ iterp,
                           float* __restrict__ out) {
    int n = blockIdx.x * blockDim.x + threadIdx.x;

    int iter = iterp ? iterp[0] : 60000;  // low word valid for LE int64 too
    int it = iter - 50000; if (it < 0) it = 0;
    double prog = (double)it / 100000.0;
    if (prog > 1.0) prog = 1.0;
    float weight = (float)(1e-3 + (5e3 - 1e-3) * prog);

    float val = 0.0f;
    if (n < NV) {
        float acc = 0.0f;
        #pragma unroll
        for (int b = 0; b < B; ++b) {
            int t = b * NV + n;
            float gb = g_best[0][t];
            int   bi = g_bidx[0][t];
            #pragma unroll
            for (int c = 1; c < NCHUNK; ++c) {
                float v = g_best[c][t];
                int   vi = g_bidx[c][t];
                if (v < gb || (v == gb && vi < bi)) { gb = v; bi = vi; }
            }
            float4 p  = g_fn[b * NF + bi];
            float4 nm = g_nm[b * NF + bi];
            const float* q = cloth_n + ((long long)b * NV + n) * 3;
            float dx = __fsub_rn(q[0], p.x);
            float dy = __fsub_rn(q[1], p.y);
            float dz = __fsub_rn(q[2], p.z);
            float dist = __fmaf_rn(dz, nm.z, __fmaf_rn(dy, nm.y, __fmul_rn(dx, nm.x)));
            float t2 = __fsub_rn(1e-3f, dist);
            t2 = t2 > 0.0f ? t2 : 0.0f;
            acc = __fadd_rn(acc, __fmul_rn(__fmul_rn(t2, t2), t2));
        }
        val = __fmul_rn(__fmul_rn(acc, 0.5f), weight);
        out[1 + n] = val;
    }

    __shared__ float sh[256];
    sh[threadIdx.x] = val;
    __syncthreads();
    for (int k = 128; k > 0; k >>= 1) {
        if (threadIdx.x < k) sh[threadIdx.x] += sh[threadIdx.x + k];
        __syncthreads();
    }
    if (threadIdx.x == 0) g_partial[blockIdx.x] = sh[0];
}

// ---------------------------------------------------------------------------
// Kernel 4: out[0] = sum of 64 block partials (1 warp, deterministic)
// ---------------------------------------------------------------------------
__global__ void red_kernel(float* __restrict__ out) {
    int l = threadIdx.x;            // 32 threads
    float s = g_partial[l] + g_partial[l + 32];
    #pragma unroll
    for (int o = 16; o > 0; o >>= 1) s += __shfl_xor_sync(0xffffffffu, s, o);
    if (l == 0) out[0] = s;
}

// ---------------------------------------------------------------------------
// Resolve inputs BY SIZE (tolerant to elements-vs-bytes conventions)
// ---------------------------------------------------------------------------
extern "C" void kernel_launch(void* const* d_in, const int* in_sizes, int n_in,
                              void* d_out, int out_size) {
    const float* cloth_curr = nullptr;
    const float* cloth_next = nullptr;
    const float* obs_curr   = nullptr;
    const float* obs_next   = nullptr;
    const int*   faces32    = nullptr;
    const int*   iterp      = nullptr;

    int n_big = 0, n_obs = 0;
    for (int i = 0; i < n_in; ++i) {
        int s = in_sizes[i];
        if (s == 98304 || s == 393216) {
            if (n_big == 0)      cloth_curr = (const float*)d_in[i];
            else if (n_big == 1) cloth_next = (const float*)d_in[i];
            else                 faces32    = (const int*)d_in[i];
            ++n_big;
        } else if (s == 786432) {
            faces32 = (const int*)d_in[i];
        } else if (s == 72000 || s == 288000) {
            if (n_obs == 0) obs_curr = (const float*)d_in[i];
            else            obs_next = (const float*)d_in[i];
            ++n_obs;
        } else if (s == 1 || s == 4 || s == 8) {
            iterp = (const int*)d_in[i];
        }
    }

    float* out = (float*)d_out;

    prep_kernel<<<(B * NF + 255) / 256, 256>>>(obs_curr, obs_next, faces32);

    dim3 grid(NV / VPC, B, NCHUNK);   // (32, 2, 8) = 512 CTAs
    nn_kernel<<<grid, T2>>>(cloth_curr);

    epi_kernel<<<NV / 256, 256>>>(cloth_next, iterp, out);
    red_kernel<<<1, 32>>>(out);
}